// round 9
// baseline (speedup 1.0000x reference)
#include <cuda_runtime.h>
#include <cuda_bf16.h>
#include <cstdint>
#include <math.h>

// Problem constants
constexpr int B_   = 4;
constexpr int N_   = 2048;
constexpr int D_   = 1024;
constexpr int MTOT = B_ * N_;  // 8192

// ---------------- scratch (static __device__, allocation-free) ----------------
__device__ __align__(1024) __nv_bfloat16 g_Xh[(size_t)MTOT * D_];
__device__ __align__(1024) __nv_bfloat16 g_Xl[(size_t)MTOT * D_];
__device__ __align__(1024) __nv_bfloat16 g_Qh[(size_t)MTOT * D_];
__device__ __align__(1024) __nv_bfloat16 g_Ql[(size_t)MTOT * D_];
__device__ __align__(1024) __nv_bfloat16 g_Kh[(size_t)MTOT * D_];
__device__ __align__(1024) __nv_bfloat16 g_Kl[(size_t)MTOT * D_];
__device__ __align__(1024) __nv_bfloat16 g_Vth[(size_t)D_ * MTOT];   // V^T [e][m]
__device__ __align__(1024) __nv_bfloat16 g_Vtl[(size_t)D_ * MTOT];
__device__ __align__(1024) __nv_bfloat16 g_Wqth[(size_t)D_ * D_];    // W^T [e][d]
__device__ __align__(1024) __nv_bfloat16 g_Wqtl[(size_t)D_ * D_];
__device__ __align__(1024) __nv_bfloat16 g_Wkth[(size_t)D_ * D_];
__device__ __align__(1024) __nv_bfloat16 g_Wktl[(size_t)D_ * D_];
__device__ __align__(1024) __nv_bfloat16 g_Wvth[(size_t)D_ * D_];
__device__ __align__(1024) __nv_bfloat16 g_Wvtl[(size_t)D_ * D_];
__device__ __align__(1024) float         g_S [(size_t)B_ * N_ * N_]; // 64 MB
__device__ __align__(1024) __nv_bfloat16 g_Ph[(size_t)B_ * N_ * N_];
__device__ __align__(1024) __nv_bfloat16 g_Pl[(size_t)B_ * N_ * N_];

// ---------------- helpers (plain sm_80-level PTX only; no 'a' features) -------
__device__ __forceinline__ uint32_t s2u(const void* p) {
    uint32_t a;
    asm("{ .reg .u64 t; cvta.to.shared.u64 t, %1; cvt.u32.u64 %0, t; }" : "=r"(a) : "l"(p));
    return a;
}
__device__ __forceinline__ void cpasync16(uint32_t dst, const void* src) {
    asm volatile("cp.async.cg.shared.global [%0], [%1], 16;" :: "r"(dst), "l"(src));
}
__device__ __forceinline__ void ldm4(uint32_t (&r)[4], uint32_t addr) {
    asm volatile("ldmatrix.sync.aligned.m8n8.x4.shared.b16 {%0,%1,%2,%3}, [%4];"
                 : "=r"(r[0]), "=r"(r[1]), "=r"(r[2]), "=r"(r[3]) : "r"(addr));
}
__device__ __forceinline__ void mma16816(float (&c)[4], const uint32_t* a,
                                         uint32_t b0, uint32_t b1) {
    asm volatile(
        "mma.sync.aligned.m16n8k16.row.col.f32.bf16.bf16.f32 "
        "{%0,%1,%2,%3}, {%4,%5,%6,%7}, {%8,%9}, {%0,%1,%2,%3};"
        : "+f"(c[0]), "+f"(c[1]), "+f"(c[2]), "+f"(c[3])
        : "r"(a[0]), "r"(a[1]), "r"(a[2]), "r"(a[3]), "r"(b0), "r"(b1));
}
// Tile row = 32 bf16 = 64B; swizzle 16B chunk index within row for conflict-free ldmatrix
__device__ __forceinline__ uint32_t swoff(int row, int kb) {
    return (uint32_t)(row * 64 + ((kb ^ ((row >> 1) & 3)) << 4));
}

// Block tile 128(M) x 256(N); warp tile 64x64; 8 warps (2 x 4); K-chunk 32.
constexpr int TILE_A  = 128 * 32 * 2;   //  8 KB per split plane
constexpr int TILE_B  = 256 * 32 * 2;   // 16 KB per split plane
constexpr int CHUNK_BYTES = 2 * TILE_A + 2 * TILE_B;  // 48 KB
constexpr int STAGES  = 4;
constexpr size_t SMEM_BYTES = (size_t)STAGES * CHUNK_BYTES;  // 192 KB -> 1 CTA/SM

// ================= split-bf16 mma.sync GEMM =================
// C[m0+m, n0+n] = sum_k (Ah+Al)[m,k] * (Bh+Bl)[n,k]   (NT, both K-major)
// OUTMODE: 0 = fp32 C, 1 = split hi/lo bf16 C. BIASMODE: 0 none, 1 by col, 2 by row.
template<int OUTMODE, int BIASMODE>
__global__ void __launch_bounds__(256, 1)
tc_gemm(const __nv_bfloat16* __restrict__ Ah, const __nv_bfloat16* __restrict__ Al,
        int lda, long sA,
        const __nv_bfloat16* __restrict__ Bh, const __nv_bfloat16* __restrict__ Bl,
        int ldb, long sB,
        float* __restrict__ Cf, __nv_bfloat16* __restrict__ Ch, __nv_bfloat16* __restrict__ Cl,
        int ldc, long sC, const float* __restrict__ bias, int Kd)
{
    extern __shared__ __align__(128) char dsm[];
    const uint32_t base = s2u(dsm);

    const int tid = threadIdx.x, wid = tid >> 5, lid = tid & 31;
    const int wm = wid >> 2, wn = wid & 3;       // 2 x 4 warps, each 64(M) x 64(N)
    const int m0 = blockIdx.y * 128, n0 = blockIdx.x * 256;
    const long z = blockIdx.z;
    Ah += z * sA; Al += z * sA; Bh += z * sB; Bl += z * sB;

    const __nv_bfloat16* aSrc[2] = { Ah + (long)m0 * lda, Al + (long)m0 * lda };
    const __nv_bfloat16* bSrc[2] = { Bh + (long)n0 * ldb, Bl + (long)n0 * ldb };

    auto load_chunk = [&](int chunk, int stage) {
        const uint32_t sb = base + (uint32_t)(stage * CHUNK_BYTES);
        #pragma unroll
        for (int p = 0; p < 2; p++) {            // A hi/lo planes: 128 rows
            const __nv_bfloat16* s = aSrc[p] + chunk * 32;
            const uint32_t tb = sb + (uint32_t)(p * TILE_A);
            #pragma unroll
            for (int i = 0; i < 2; i++) {
                int o = i * 256 + tid;           // 512 x 16B
                int r = o >> 2, kb = o & 3;
                cpasync16(tb + swoff(r, kb), s + (long)r * lda + kb * 8);
            }
        }
        #pragma unroll
        for (int p = 0; p < 2; p++) {            // B hi/lo planes: 256 rows
            const __nv_bfloat16* s = bSrc[p] + chunk * 32;
            const uint32_t tb = sb + (uint32_t)(2 * TILE_A + p * TILE_B);
            #pragma unroll
            for (int i = 0; i < 4; i++) {
                int o = i * 256 + tid;           // 1024 x 16B
                int r = o >> 2, kb = o & 3;
                cpasync16(tb + swoff(r, kb), s + (long)r * ldb + kb * 8);
            }
        }
        asm volatile("cp.async.commit_group;" ::: "memory");
    };

    float acc[4][8][4];
    #pragma unroll
    for (int i = 0; i < 4; i++)
        #pragma unroll
        for (int t = 0; t < 8; t++)
            #pragma unroll
            for (int j = 0; j < 4; j++) acc[i][t][j] = 0.0f;

    const int nk = Kd / 32;
    load_chunk(0, 0); load_chunk(1, 1);

    const int rA  = (lid & 7) + ((lid >> 3) & 1) * 8;  // ldmatrix row-in-16
    const int kbh = (lid >> 4) & 1;                    // ldmatrix k-half

    for (int k = 0; k < nk; k++) {
        if (k + 1 < nk) asm volatile("cp.async.wait_group 1;" ::: "memory");
        else            asm volatile("cp.async.wait_group 0;" ::: "memory");
        __syncthreads();
        // Barrier proves chunk k-1's compute finished everywhere; its stage
        // equals (k+2)&3 with 4 stages — safe to refill below (after the first
        // MMA pass, so LDGSTS issue doesn't delay the first fragments).

        const uint32_t sb  = base + (uint32_t)((k & 3) * CHUNK_BYTES);
        const uint32_t tAh = sb;
        const uint32_t tAl = sb + TILE_A;
        const uint32_t tBh = sb + 2 * TILE_A;
        const uint32_t tBl = sb + 2 * TILE_A + TILE_B;

        #pragma unroll
        for (int p = 0; p < 2; p++) {            // two k16 steps per 32-chunk
            const uint32_t kxor = (uint32_t)(((2 * p + kbh) ^ ((rA >> 1) & 3)) << 4);
            uint32_t fAh[4][4], fAl[4][4], fBh[4][4], fBl[4][4];
            #pragma unroll
            for (int i = 0; i < 4; i++) {        // A: 64 rows, hi first
                const uint32_t rb = (uint32_t)((wm * 64 + i * 16 + rA) * 64);
                ldm4(fAh[i], tAh + rb + kxor);
            }
            #pragma unroll
            for (int q = 0; q < 4; q++) {        // B: 64 cols, hi first
                const uint32_t rb = (uint32_t)((wn * 64 + q * 16 + rA) * 64);
                ldm4(fBh[q], tBh + rb + kxor);
            }
            #pragma unroll
            for (int i = 0; i < 4; i++) {
                const uint32_t rb = (uint32_t)((wm * 64 + i * 16 + rA) * 64);
                ldm4(fAl[i], tAl + rb + kxor);
            }
            #pragma unroll
            for (int q = 0; q < 4; q++) {
                const uint32_t rb = (uint32_t)((wn * 64 + q * 16 + rA) * 64);
                ldm4(fBl[q], tBl + rb + kxor);
            }
            // pass 1: hh (only needs the first 8 LDSM)
            #pragma unroll
            for (int i = 0; i < 4; i++)
                #pragma unroll
                for (int nt = 0; nt < 8; nt++) {
                    const int q = nt >> 1, sx = nt & 1;
                    mma16816(acc[i][nt], fAh[i], fBh[q][sx], fBh[q][sx + 2]);
                }
            // overlap the global prefetch with the lo passes
            if (p == 0 && k + 2 < nk) load_chunk(k + 2, (k + 2) & 3);
            // pass 2: hl
            #pragma unroll
            for (int i = 0; i < 4; i++)
                #pragma unroll
                for (int nt = 0; nt < 8; nt++) {
                    const int q = nt >> 1, sx = nt & 1;
                    mma16816(acc[i][nt], fAh[i], fBl[q][sx], fBl[q][sx + 2]);
                }
            // pass 3: lh
            #pragma unroll
            for (int i = 0; i < 4; i++)
                #pragma unroll
                for (int nt = 0; nt < 8; nt++) {
                    const int q = nt >> 1, sx = nt & 1;
                    mma16816(acc[i][nt], fAl[i], fBh[q][sx], fBh[q][sx + 2]);
                }
        }
    }

    // ---------------- epilogue: direct register -> gmem ----------------
    #pragma unroll
    for (int i = 0; i < 4; i++)
        #pragma unroll
        for (int nt = 0; nt < 8; nt++) {
            const int row = m0 + wm * 64 + i * 16 + (lid >> 2);
            const int col = n0 + wn * 64 + nt * 8 + 2 * (lid & 3);
            float v0 = acc[i][nt][0], v1 = acc[i][nt][1];
            float v2 = acc[i][nt][2], v3 = acc[i][nt][3];
            if (BIASMODE == 1) {
                const float b0 = bias[col], b1 = bias[col + 1];
                v0 += b0; v1 += b1; v2 += b0; v3 += b1;
            } else if (BIASMODE == 2) {
                const float b0 = bias[row], b1 = bias[row + 8];
                v0 += b0; v1 += b0; v2 += b1; v3 += b1;
            }
            const long o0 = (long)row * ldc + col + z * sC;
            const long o1 = o0 + 8L * ldc;
            if (OUTMODE == 0) {
                *(float2*)(Cf + o0) = make_float2(v0, v1);
                *(float2*)(Cf + o1) = make_float2(v2, v3);
            } else {
                __nv_bfloat16 h0 = __float2bfloat16(v0), h1 = __float2bfloat16(v1);
                __nv_bfloat16 h2 = __float2bfloat16(v2), h3 = __float2bfloat16(v3);
                __nv_bfloat16 l0 = __float2bfloat16(v0 - __bfloat162float(h0));
                __nv_bfloat16 l1 = __float2bfloat16(v1 - __bfloat162float(h1));
                __nv_bfloat16 l2 = __float2bfloat16(v2 - __bfloat162float(h2));
                __nv_bfloat16 l3 = __float2bfloat16(v3 - __bfloat162float(h3));
                __nv_bfloat162 ph0; ph0.x = h0; ph0.y = h1;
                __nv_bfloat162 ph1; ph1.x = h2; ph1.y = h3;
                __nv_bfloat162 pl0; pl0.x = l0; pl0.y = l1;
                __nv_bfloat162 pl1; pl1.x = l2; pl1.y = l3;
                *(__nv_bfloat162*)(Ch + o0) = ph0;
                *(__nv_bfloat162*)(Ch + o1) = ph1;
                *(__nv_bfloat162*)(Cl + o0) = pl0;
                *(__nv_bfloat162*)(Cl + o1) = pl1;
            }
        }
}

// ================= prep kernels =================
__global__ void __launch_bounds__(256)
split_x_kernel(const float* __restrict__ X, __nv_bfloat16* __restrict__ Xh,
               __nv_bfloat16* __restrict__ Xl)
{
    const long i = ((long)blockIdx.x * 256 + threadIdx.x) * 4;
    float4 v = *(const float4*)(X + i);
    float vv[4] = { v.x, v.y, v.z, v.w };
    __nv_bfloat16 h[4], l[4];
    #pragma unroll
    for (int j = 0; j < 4; j++) {
        h[j] = __float2bfloat16(vv[j]);
        l[j] = __float2bfloat16(vv[j] - __bfloat162float(h[j]));
    }
    __nv_bfloat162 h01, h23, l01, l23;
    h01.x = h[0]; h01.y = h[1]; h23.x = h[2]; h23.y = h[3];
    l01.x = l[0]; l01.y = l[1]; l23.x = l[2]; l23.y = l[3];
    *(__nv_bfloat162*)(Xh + i)     = h01;
    *(__nv_bfloat162*)(Xh + i + 2) = h23;
    *(__nv_bfloat162*)(Xl + i)     = l01;
    *(__nv_bfloat162*)(Xl + i + 2) = l23;
}

// Transpose + split 1024x1024 weights: T[e][d] = W[d][e]
__global__ void __launch_bounds__(256)
transpose_split_kernel(const float* __restrict__ W0, const float* __restrict__ W1,
                       const float* __restrict__ W2,
                       __nv_bfloat16* __restrict__ T0h, __nv_bfloat16* __restrict__ T0l,
                       __nv_bfloat16* __restrict__ T1h, __nv_bfloat16* __restrict__ T1l,
                       __nv_bfloat16* __restrict__ T2h, __nv_bfloat16* __restrict__ T2l)
{
    __shared__ float t[32][33];
    const float* W = (blockIdx.z == 0) ? W0 : (blockIdx.z == 1) ? W1 : W2;
    __nv_bfloat16* Th = (blockIdx.z == 0) ? T0h : (blockIdx.z == 1) ? T1h : T2h;
    __nv_bfloat16* Tl = (blockIdx.z == 0) ? T0l : (blockIdx.z == 1) ? T1l : T2l;

    const int tx = threadIdx.x, ty = threadIdx.y;       // block 32x8
    const int e = blockIdx.x * 32 + tx;
    const int d0 = blockIdx.y * 32;
    #pragma unroll
    for (int i = ty; i < 32; i += 8)
        t[i][tx] = W[(long)(d0 + i) * D_ + e];
    __syncthreads();
    const int eo = blockIdx.x * 32;
    const int d = d0 + tx;
    #pragma unroll
    for (int i = ty; i < 32; i += 8) {
        float w = t[tx][i];
        __nv_bfloat16 h = __float2bfloat16(w);
        __nv_bfloat16 l = __float2bfloat16(w - __bfloat162float(h));
        Th[(long)(eo + i) * D_ + d] = h;
        Tl[(long)(eo + i) * D_ + d] = l;
    }
}

// Row softmax over S (length 2048), write split-bf16 P.
__global__ void __launch_bounds__(256)
softmax_split_kernel(const float* __restrict__ S, __nv_bfloat16* __restrict__ Ph,
                     __nv_bfloat16* __restrict__ Pl)
{
    const long row = blockIdx.x;
    const float* p = S + row * (long)N_;
    const int tid = threadIdx.x;

    float v[8];
    float mx = -1e30f;
    #pragma unroll
    for (int i = 0; i < 8; i++) { v[i] = p[tid + i * 256]; mx = fmaxf(mx, v[i]); }

    __shared__ float redm[8], reds[8];
    #pragma unroll
    for (int o = 16; o; o >>= 1) mx = fmaxf(mx, __shfl_xor_sync(0xffffffffu, mx, o));
    if ((tid & 31) == 0) redm[tid >> 5] = mx;
    __syncthreads();
    if (tid == 0) {
        float m = redm[0];
        #pragma unroll
        for (int i = 1; i < 8; i++) m = fmaxf(m, redm[i]);
        redm[0] = m;
    }
    __syncthreads();
    mx = redm[0];

    float s = 0.0f;
    #pragma unroll
    for (int i = 0; i < 8; i++) { v[i] = __expf(v[i] - mx); s += v[i]; }
    #pragma unroll
    for (int o = 16; o; o >>= 1) s += __shfl_xor_sync(0xffffffffu, s, o);
    if ((tid & 31) == 0) reds[tid >> 5] = s;
    __syncthreads();
    if (tid == 0) {
        float m = 0.0f;
        #pragma unroll
        for (int i = 0; i < 8; i++) m += reds[i];
        reds[0] = m;
    }
    __syncthreads();
    const float inv = 1.0f / reds[0];

    #pragma unroll
    for (int i = 0; i < 8; i++) {
        float w = v[i] * inv;
        __nv_bfloat16 h = __float2bfloat16(w);
        __nv_bfloat16 l = __float2bfloat16(w - __bfloat162float(h));
        Ph[row * (long)N_ + tid + i * 256] = h;
        Pl[row * (long)N_ + tid + i * 256] = l;
    }
}

// ================= host glue =================
extern "C" void kernel_launch(void* const* d_in, const int* in_sizes, int n_in,
                              void* d_out, int out_size)
{
    const float* X  = (const float*)d_in[0];
    const float* Wq = (const float*)d_in[1];
    const float* bq = (const float*)d_in[2];
    const float* Wk = (const float*)d_in[3];
    const float* bk = (const float*)d_in[4];
    const float* Wv = (const float*)d_in[5];
    const float* bv = (const float*)d_in[6];
    float* out = (float*)d_out;

    __nv_bfloat16 *Xh, *Xl, *Qh, *Ql, *Kh, *Kl, *Vth, *Vtl;
    __nv_bfloat16 *Wqth, *Wqtl, *Wkth, *Wktl, *Wvth, *Wvtl, *Ph, *Pl;
    float* S;
    cudaGetSymbolAddress((void**)&Xh, g_Xh);   cudaGetSymbolAddress((void**)&Xl, g_Xl);
    cudaGetSymbolAddress((void**)&Qh, g_Qh);   cudaGetSymbolAddress((void**)&Ql, g_Ql);
    cudaGetSymbolAddress((void**)&Kh, g_Kh);   cudaGetSymbolAddress((void**)&Kl, g_Kl);
    cudaGetSymbolAddress((void**)&Vth, g_Vth); cudaGetSymbolAddress((void**)&Vtl, g_Vtl);
    cudaGetSymbolAddress((void**)&Wqth, g_Wqth); cudaGetSymbolAddress((void**)&Wqtl, g_Wqtl);
    cudaGetSymbolAddress((void**)&Wkth, g_Wkth); cudaGetSymbolAddress((void**)&Wktl, g_Wktl);
    cudaGetSymbolAddress((void**)&Wvth, g_Wvth); cudaGetSymbolAddress((void**)&Wvtl, g_Wvtl);
    cudaGetSymbolAddress((void**)&Ph, g_Ph);   cudaGetSymbolAddress((void**)&Pl, g_Pl);
    cudaGetSymbolAddress((void**)&S, g_S);

    cudaFuncSetAttribute((const void*)tc_gemm<1, 1>, cudaFuncAttributeMaxDynamicSharedMemorySize, (int)SMEM_BYTES);
    cudaFuncSetAttribute((const void*)tc_gemm<1, 2>, cudaFuncAttributeMaxDynamicSharedMemorySize, (int)SMEM_BYTES);
    cudaFuncSetAttribute((const void*)tc_gemm<0, 0>, cudaFuncAttributeMaxDynamicSharedMemorySize, (int)SMEM_BYTES);

    dim3 blk(256);

    // 0) split X, transpose+split weights
    split_x_kernel<<<(MTOT * D_) / 1024, 256>>>(X, Xh, Xl);
    transpose_split_kernel<<<dim3(32, 32, 3), dim3(32, 8)>>>(
        Wq, Wk, Wv, Wqth, Wqtl, Wkth, Wktl, Wvth, Wvtl);

    // 1) Q = X Wq^T + bq ; K = X Wk^T + bk   (split-bf16 outputs)  [N=1024 -> 4 col-blocks]
    tc_gemm<1, 1><<<dim3(4, 64, 1), blk, SMEM_BYTES>>>(
        Xh, Xl, D_, 0, Wqth, Wqtl, D_, 0, nullptr, Qh, Ql, D_, 0, bq, D_);
    tc_gemm<1, 1><<<dim3(4, 64, 1), blk, SMEM_BYTES>>>(
        Xh, Xl, D_, 0, Wkth, Wktl, D_, 0, nullptr, Kh, Kl, D_, 0, bk, D_);
    // 1b) V^T[e,m] = Wv^T X^T + bv (bias by row e)  [M=1024, N=8192]
    tc_gemm<1, 2><<<dim3(32, 8, 1), blk, SMEM_BYTES>>>(
        Wvth, Wvtl, D_, 0, Xh, Xl, D_, 0, nullptr, Vth, Vtl, MTOT, 0, bv, D_);

    // 2) S = Q K^T per batch (fp32)  [M=N=2048]
    tc_gemm<0, 0><<<dim3(8, 16, B_), blk, SMEM_BYTES>>>(
        Qh, Ql, D_, (long)N_ * D_, Kh, Kl, D_, (long)N_ * D_,
        S, nullptr, nullptr, N_, (long)N_ * N_, nullptr, D_);

    // 3) softmax + split P
    softmax_split_kernel<<<B_ * N_, 256>>>(S, Ph, Pl);

    // 4) out = P V per batch (NT against V^T, fp32 out)  [M=2048, N=1024, K=2048]
    tc_gemm<0, 0><<<dim3(4, 16, B_), blk, SMEM_BYTES>>>(
        Ph, Pl, N_, (long)N_ * N_, Vth, Vtl, MTOT, (long)N_,
        out, nullptr, nullptr, D_, (long)N_ * D_, nullptr, N_);
}

// round 12
// speedup vs baseline: 1.0630x; 1.0630x over previous
#include <cuda_runtime.h>
#include <cuda_bf16.h>
#include <cstdint>
#include <math.h>

// Problem constants
constexpr int B_   = 4;
constexpr int N_   = 2048;
constexpr int D_   = 1024;
constexpr int MTOT = B_ * N_;  // 8192

// ---------------- scratch (static __device__, allocation-free) ----------------
__device__ __align__(1024) __nv_bfloat16 g_Xh[(size_t)MTOT * D_];
__device__ __align__(1024) __nv_bfloat16 g_Xl[(size_t)MTOT * D_];
__device__ __align__(1024) __nv_bfloat16 g_Qh[(size_t)MTOT * D_];
__device__ __align__(1024) __nv_bfloat16 g_Ql[(size_t)MTOT * D_];
__device__ __align__(1024) __nv_bfloat16 g_Kh[(size_t)MTOT * D_];
__device__ __align__(1024) __nv_bfloat16 g_Kl[(size_t)MTOT * D_];
__device__ __align__(1024) __nv_bfloat16 g_Vh[(size_t)MTOT * D_];    // V row-major [m][e]
__device__ __align__(1024) __nv_bfloat16 g_Vl[(size_t)MTOT * D_];
__device__ __align__(1024) __nv_bfloat16 g_Vth[(size_t)D_ * MTOT];   // V^T [e][m]
__device__ __align__(1024) __nv_bfloat16 g_Vtl[(size_t)D_ * MTOT];
__device__ __align__(1024) __nv_bfloat16 g_Wqth[(size_t)D_ * D_];    // W^T [e][d]
__device__ __align__(1024) __nv_bfloat16 g_Wqtl[(size_t)D_ * D_];
__device__ __align__(1024) __nv_bfloat16 g_Wkth[(size_t)D_ * D_];
__device__ __align__(1024) __nv_bfloat16 g_Wktl[(size_t)D_ * D_];
__device__ __align__(1024) __nv_bfloat16 g_Wvth[(size_t)D_ * D_];
__device__ __align__(1024) __nv_bfloat16 g_Wvtl[(size_t)D_ * D_];
__device__ __align__(1024) float         g_S [(size_t)B_ * N_ * N_]; // 64 MB
__device__ __align__(1024) __nv_bfloat16 g_Ph[(size_t)B_ * N_ * N_];
__device__ __align__(1024) __nv_bfloat16 g_Pl[(size_t)B_ * N_ * N_];

// ---------------- helpers (plain sm_80-level PTX only; no 'a' features) -------
__device__ __forceinline__ uint32_t s2u(const void* p) {
    uint32_t a;
    asm("{ .reg .u64 t; cvta.to.shared.u64 t, %1; cvt.u32.u64 %0, t; }" : "=r"(a) : "l"(p));
    return a;
}
__device__ __forceinline__ void cpasync16(uint32_t dst, const void* src) {
    asm volatile("cp.async.cg.shared.global [%0], [%1], 16;" :: "r"(dst), "l"(src));
}
__device__ __forceinline__ void ldm4(uint32_t (&r)[4], uint32_t addr) {
    asm volatile("ldmatrix.sync.aligned.m8n8.x4.shared.b16 {%0,%1,%2,%3}, [%4];"
                 : "=r"(r[0]), "=r"(r[1]), "=r"(r[2]), "=r"(r[3]) : "r"(addr));
}
__device__ __forceinline__ void mma16816(float (&c)[4], const uint32_t* a,
                                         uint32_t b0, uint32_t b1) {
    asm volatile(
        "mma.sync.aligned.m16n8k16.row.col.f32.bf16.bf16.f32 "
        "{%0,%1,%2,%3}, {%4,%5,%6,%7}, {%8,%9}, {%0,%1,%2,%3};"
        : "+f"(c[0]), "+f"(c[1]), "+f"(c[2]), "+f"(c[3])
        : "r"(a[0]), "r"(a[1]), "r"(a[2]), "r"(a[3]), "r"(b0), "r"(b1));
}
// Tile row = 32 bf16 = 64B; swizzle 16B chunk index within row for conflict-free ldmatrix
__device__ __forceinline__ uint32_t swoff(int row, int kb) {
    return (uint32_t)(row * 64 + ((kb ^ ((row >> 1) & 3)) << 4));
}

constexpr int TILE_BYTES = 128 * 32 * 2;     // 8 KB: 128 rows x 32 bf16
constexpr int STAGES     = 3;
constexpr size_t SMEM_BYTES = (size_t)STAGES * 4 * TILE_BYTES;  // 96 KB -> 2 CTAs/SM

// ---------------- shared GEMM mainloop ----------------
// Computes the 128x128 split-bf16 NT GEMM for one block tile into acc.
__device__ __forceinline__ void gemm_mainloop(
    uint32_t base, int tid, int wid, int lid, int wm, int wn,
    const __nv_bfloat16* aH, const __nv_bfloat16* aL, int lda,
    const __nv_bfloat16* bH, const __nv_bfloat16* bL, int ldb,
    int Kd, float (&acc)[4][4][4])
{
    const __nv_bfloat16* srcs[4] = { aH, aL, bH, bL };
    const int ldsv[4] = { lda, lda, ldb, ldb };

    auto load_chunk = [&](int chunk, int stage) {
        #pragma unroll
        for (int p = 0; p < 4; p++) {
            const __nv_bfloat16* s = srcs[p] + chunk * 32;
            const int ld = ldsv[p];
            const uint32_t tb = base + (uint32_t)((stage * 4 + p) * TILE_BYTES);
            #pragma unroll
            for (int i = 0; i < 2; i++) {
                int o = i * 256 + tid;          // 512 chunks of 16B
                int r = o >> 2, kb = o & 3;
                cpasync16(tb + swoff(r, kb), s + (long)r * ld + kb * 8);
            }
        }
        asm volatile("cp.async.commit_group;" ::: "memory");
    };

    const int nk = Kd / 32;
    load_chunk(0, 0); load_chunk(1, 1);

    const int rA  = (lid & 7) + ((lid >> 3) & 1) * 8;  // ldmatrix row-in-16
    const int kbh = (lid >> 4) & 1;                    // ldmatrix k-half

    int stage = 0;      // stage of chunk k
    int pstage = 2;     // stage of chunk k+2 == stage of chunk k-1

    for (int k = 0; k < nk; k++) {
        if (k + 1 < nk) asm volatile("cp.async.wait_group 1;" ::: "memory");
        else            asm volatile("cp.async.wait_group 0;" ::: "memory");
        __syncthreads();
        // Barrier proves chunk k-1's compute finished everywhere; its stage
        // equals (k+2)%3 — free to refill now. ONE barrier per chunk.
        if (k + 2 < nk) load_chunk(k + 2, pstage);

        const uint32_t sb  = base + (uint32_t)(stage * 4 * TILE_BYTES);
        const uint32_t tAh = sb;
        const uint32_t tAl = sb + TILE_BYTES;
        const uint32_t tBh = sb + 2 * TILE_BYTES;
        const uint32_t tBl = sb + 3 * TILE_BYTES;

        #pragma unroll
        for (int p = 0; p < 2; p++) {            // two k16 steps per 32-chunk
            // All our fragment rows differ by multiples of 16, so the swizzle
            // XOR term (kb ^ (row>>1)&3) is uniform across them.
            const uint32_t kxor = (uint32_t)(((2 * p + kbh) ^ ((rA >> 1) & 3)) << 4);
            uint32_t fAh[4][4], fAl[4][4], fBh[2][4], fBl[2][4];
            #pragma unroll
            for (int i = 0; i < 4; i++) {
                const uint32_t rb = (uint32_t)((wm * 64 + i * 16 + rA) * 64);
                ldm4(fAh[i], tAh + rb + kxor);
                ldm4(fAl[i], tAl + rb + kxor);
            }
            #pragma unroll
            for (int q = 0; q < 2; q++) {
                const uint32_t rb = (uint32_t)((wn * 32 + q * 16 + rA) * 64);
                ldm4(fBh[q], tBh + rb + kxor);
                ldm4(fBl[q], tBl + rb + kxor);
            }
            // Three passes over all 16 accumulator tiles: RAW distance 16 MMAs.
            #pragma unroll
            for (int i = 0; i < 4; i++)
                #pragma unroll
                for (int nt = 0; nt < 4; nt++) {
                    const int q = nt >> 1, sx = nt & 1;
                    mma16816(acc[i][nt], fAh[i], fBh[q][sx], fBh[q][sx + 2]);
                }
            #pragma unroll
            for (int i = 0; i < 4; i++)
                #pragma unroll
                for (int nt = 0; nt < 4; nt++) {
                    const int q = nt >> 1, sx = nt & 1;
                    mma16816(acc[i][nt], fAh[i], fBl[q][sx], fBl[q][sx + 2]);
                }
            #pragma unroll
            for (int i = 0; i < 4; i++)
                #pragma unroll
                for (int nt = 0; nt < 4; nt++) {
                    const int q = nt >> 1, sx = nt & 1;
                    mma16816(acc[i][nt], fAl[i], fBh[q][sx], fBh[q][sx + 2]);
                }
        }
        stage  = (stage  == STAGES - 1) ? 0 : stage + 1;
        pstage = (pstage == STAGES - 1) ? 0 : pstage + 1;
    }
}

// ================= generic split-bf16 GEMM (S = QK^T, out = PV) =================
// OUTMODE: 0 = fp32 C, 1 = split hi/lo bf16 C. BIASMODE: 0 none, 1 by col.
template<int OUTMODE, int BIASMODE>
__global__ void __launch_bounds__(256, 2)
tc_gemm(const __nv_bfloat16* __restrict__ Ah, const __nv_bfloat16* __restrict__ Al,
        int lda, long sA,
        const __nv_bfloat16* __restrict__ Bh, const __nv_bfloat16* __restrict__ Bl,
        int ldb, long sB,
        float* __restrict__ Cf, __nv_bfloat16* __restrict__ Ch, __nv_bfloat16* __restrict__ Cl,
        int ldc, long sC, const float* __restrict__ bias, int Kd)
{
    extern __shared__ __align__(128) char dsm[];
    const uint32_t base = s2u(dsm);
    const int tid = threadIdx.x, wid = tid >> 5, lid = tid & 31;
    const int wm = wid >> 2, wn = wid & 3;
    const int m0 = blockIdx.y * 128, n0 = blockIdx.x * 128;
    const long z = blockIdx.z;

    float acc[4][4][4];
    #pragma unroll
    for (int i = 0; i < 4; i++)
        #pragma unroll
        for (int t = 0; t < 4; t++)
            #pragma unroll
            for (int j = 0; j < 4; j++) acc[i][t][j] = 0.0f;

    gemm_mainloop(base, tid, wid, lid, wm, wn,
                  Ah + z * sA + (long)m0 * lda, Al + z * sA + (long)m0 * lda, lda,
                  Bh + z * sB + (long)n0 * ldb, Bl + z * sB + (long)n0 * ldb, ldb,
                  Kd, acc);

    #pragma unroll
    for (int i = 0; i < 4; i++)
        #pragma unroll
        for (int nt = 0; nt < 4; nt++) {
            const int row = m0 + wm * 64 + i * 16 + (lid >> 2);
            const int col = n0 + wn * 32 + nt * 8 + 2 * (lid & 3);
            float v0 = acc[i][nt][0], v1 = acc[i][nt][1];
            float v2 = acc[i][nt][2], v3 = acc[i][nt][3];
            if (BIASMODE == 1) {
                const float b0 = bias[col], b1 = bias[col + 1];
                v0 += b0; v1 += b1; v2 += b0; v3 += b1;
            }
            const long o0 = (long)row * ldc + col + z * sC;
            const long o1 = o0 + 8L * ldc;
            if (OUTMODE == 0) {
                *(float2*)(Cf + o0) = make_float2(v0, v1);
                *(float2*)(Cf + o1) = make_float2(v2, v3);
            } else {
                __nv_bfloat16 h0 = __float2bfloat16(v0), h1 = __float2bfloat16(v1);
                __nv_bfloat16 h2 = __float2bfloat16(v2), h3 = __float2bfloat16(v3);
                __nv_bfloat16 l0 = __float2bfloat16(v0 - __bfloat162float(h0));
                __nv_bfloat16 l1 = __float2bfloat16(v1 - __bfloat162float(h1));
                __nv_bfloat16 l2 = __float2bfloat16(v2 - __bfloat162float(h2));
                __nv_bfloat16 l3 = __float2bfloat16(v3 - __bfloat162float(h3));
                __nv_bfloat162 ph0; ph0.x = h0; ph0.y = h1;
                __nv_bfloat162 ph1; ph1.x = h2; ph1.y = h3;
                __nv_bfloat162 pl0; pl0.x = l0; pl0.y = l1;
                __nv_bfloat162 pl1; pl1.x = l2; pl1.y = l3;
                *(__nv_bfloat162*)(Ch + o0) = ph0;
                *(__nv_bfloat162*)(Ch + o1) = ph1;
                *(__nv_bfloat162*)(Cl + o0) = pl0;
                *(__nv_bfloat162*)(Cl + o1) = pl1;
            }
        }
}

// ================= fused QKV projection: one launch, z picks {Q,K,V} ==========
__global__ void __launch_bounds__(256, 2)
qkv_gemm(const __nv_bfloat16* __restrict__ Xh, const __nv_bfloat16* __restrict__ Xl,
         const __nv_bfloat16* __restrict__ Wqh, const __nv_bfloat16* __restrict__ Wql,
         const __nv_bfloat16* __restrict__ Wkh, const __nv_bfloat16* __restrict__ Wkl,
         const __nv_bfloat16* __restrict__ Wvh, const __nv_bfloat16* __restrict__ Wvl,
         const float* __restrict__ bq, const float* __restrict__ bk,
         const float* __restrict__ bv,
         __nv_bfloat16* __restrict__ Qh, __nv_bfloat16* __restrict__ Ql,
         __nv_bfloat16* __restrict__ Kh, __nv_bfloat16* __restrict__ Kl,
         __nv_bfloat16* __restrict__ Vh, __nv_bfloat16* __restrict__ Vl)
{
    extern __shared__ __align__(128) char dsm[];
    const uint32_t base = s2u(dsm);
    const int tid = threadIdx.x, wid = tid >> 5, lid = tid & 31;
    const int wm = wid >> 2, wn = wid & 3;
    const int m0 = blockIdx.y * 128, n0 = blockIdx.x * 128;
    const int zz = blockIdx.z;

    const __nv_bfloat16* Bh = (zz == 0) ? Wqh : (zz == 1) ? Wkh : Wvh;
    const __nv_bfloat16* Bl = (zz == 0) ? Wql : (zz == 1) ? Wkl : Wvl;
    const float* bias       = (zz == 0) ? bq  : (zz == 1) ? bk  : bv;
    __nv_bfloat16* Ch       = (zz == 0) ? Qh  : (zz == 1) ? Kh  : Vh;
    __nv_bfloat16* Cl       = (zz == 0) ? Ql  : (zz == 1) ? Kl  : Vl;

    float acc[4][4][4];
    #pragma unroll
    for (int i = 0; i < 4; i++)
        #pragma unroll
        for (int t = 0; t < 4; t++)
            #pragma unroll
            for (int j = 0; j < 4; j++) acc[i][t][j] = 0.0f;

    gemm_mainloop(base, tid, wid, lid, wm, wn,
                  Xh + (long)m0 * D_, Xl + (long)m0 * D_, D_,
                  Bh + (long)n0 * D_, Bl + (long)n0 * D_, D_,
                  D_, acc);

    #pragma unroll
    for (int i = 0; i < 4; i++)
        #pragma unroll
        for (int nt = 0; nt < 4; nt++) {
            const int row = m0 + wm * 64 + i * 16 + (lid >> 2);
            const int col = n0 + wn * 32 + nt * 8 + 2 * (lid & 3);
            const float b0 = bias[col], b1 = bias[col + 1];
            float v0 = acc[i][nt][0] + b0, v1 = acc[i][nt][1] + b1;
            float v2 = acc[i][nt][2] + b0, v3 = acc[i][nt][3] + b1;
            const long o0 = (long)row * D_ + col;
            const long o1 = o0 + 8L * D_;
            __nv_bfloat16 h0 = __float2bfloat16(v0), h1 = __float2bfloat16(v1);
            __nv_bfloat16 h2 = __float2bfloat16(v2), h3 = __float2bfloat16(v3);
            __nv_bfloat16 l0 = __float2bfloat16(v0 - __bfloat162float(h0));
            __nv_bfloat16 l1 = __float2bfloat16(v1 - __bfloat162float(h1));
            __nv_bfloat16 l2 = __float2bfloat16(v2 - __bfloat162float(h2));
            __nv_bfloat16 l3 = __float2bfloat16(v3 - __bfloat162float(h3));
            __nv_bfloat162 ph0; ph0.x = h0; ph0.y = h1;
            __nv_bfloat162 ph1; ph1.x = h2; ph1.y = h3;
            __nv_bfloat162 pl0; pl0.x = l0; pl0.y = l1;
            __nv_bfloat162 pl1; pl1.x = l2; pl1.y = l3;
            *(__nv_bfloat162*)(Ch + o0) = ph0;
            *(__nv_bfloat162*)(Ch + o1) = ph1;
            *(__nv_bfloat162*)(Cl + o0) = pl0;
            *(__nv_bfloat162*)(Cl + o1) = pl1;
        }
}

// ================= prep kernels =================
__global__ void __launch_bounds__(256)
split_x_kernel(const float* __restrict__ X, __nv_bfloat16* __restrict__ Xh,
               __nv_bfloat16* __restrict__ Xl)
{
    const long i = ((long)blockIdx.x * 256 + threadIdx.x) * 4;
    float4 v = *(const float4*)(X + i);
    float vv[4] = { v.x, v.y, v.z, v.w };
    __nv_bfloat16 h[4], l[4];
    #pragma unroll
    for (int j = 0; j < 4; j++) {
        h[j] = __float2bfloat16(vv[j]);
        l[j] = __float2bfloat16(vv[j] - __bfloat162float(h[j]));
    }
    __nv_bfloat162 h01, h23, l01, l23;
    h01.x = h[0]; h01.y = h[1]; h23.x = h[2]; h23.y = h[3];
    l01.x = l[0]; l01.y = l[1]; l23.x = l[2]; l23.y = l[3];
    *(__nv_bfloat162*)(Xh + i)     = h01;
    *(__nv_bfloat162*)(Xh + i + 2) = h23;
    *(__nv_bfloat162*)(Xl + i)     = l01;
    *(__nv_bfloat162*)(Xl + i + 2) = l23;
}

// Transpose + split 1024x1024 weights: T[e][d] = W[d][e]
__global__ void __launch_bounds__(256)
transpose_split_kernel(const float* __restrict__ W0, const float* __restrict__ W1,
                       const float* __restrict__ W2,
                       __nv_bfloat16* __restrict__ T0h, __nv_bfloat16* __restrict__ T0l,
                       __nv_bfloat16* __restrict__ T1h, __nv_bfloat16* __restrict__ T1l,
                       __nv_bfloat16* __restrict__ T2h, __nv_bfloat16* __restrict__ T2l)
{
    __shared__ float t[32][33];
    const float* W = (blockIdx.z == 0) ? W0 : (blockIdx.z == 1) ? W1 : W2;
    __nv_bfloat16* Th = (blockIdx.z == 0) ? T0h : (blockIdx.z == 1) ? T1h : T2h;
    __nv_bfloat16* Tl = (blockIdx.z == 0) ? T0l : (blockIdx.z == 1) ? T1l : T2l;

    const int tx = threadIdx.x, ty = threadIdx.y;       // block 32x8
    const int e = blockIdx.x * 32 + tx;
    const int d0 = blockIdx.y * 32;
    #pragma unroll
    for (int i = ty; i < 32; i += 8)
        t[i][tx] = W[(long)(d0 + i) * D_ + e];
    __syncthreads();
    const int eo = blockIdx.x * 32;
    const int d = d0 + tx;
    #pragma unroll
    for (int i = ty; i < 32; i += 8) {
        float w = t[tx][i];
        __nv_bfloat16 h = __float2bfloat16(w);
        __nv_bfloat16 l = __float2bfloat16(w - __bfloat162float(h));
        Th[(long)(eo + i) * D_ + d] = h;
        Tl[(long)(eo + i) * D_ + d] = l;
    }
}

// Transpose V planes: Vt[e][m] = V[m][e]  (bf16, both planes via blockIdx.z)
__global__ void __launch_bounds__(256)
transpose_v_kernel(const __nv_bfloat16* __restrict__ V0, const __nv_bfloat16* __restrict__ V1,
                   __nv_bfloat16* __restrict__ T0, __nv_bfloat16* __restrict__ T1)
{
    __shared__ __nv_bfloat16 t[32][33];
    const __nv_bfloat16* V = (blockIdx.z == 0) ? V0 : V1;
    __nv_bfloat16* T       = (blockIdx.z == 0) ? T0 : T1;

    const int tx = threadIdx.x, ty = threadIdx.y;       // block 32x8
    const int e0 = blockIdx.x * 32;
    const int m0 = blockIdx.y * 32;
    #pragma unroll
    for (int i = ty; i < 32; i += 8)
        t[i][tx] = V[(long)(m0 + i) * D_ + e0 + tx];    // read rows of V (coalesced)
    __syncthreads();
    #pragma unroll
    for (int i = ty; i < 32; i += 8)
        T[(long)(e0 + i) * MTOT + m0 + tx] = t[tx][i];  // write rows of Vt (coalesced)
}

// Row softmax over S (length 2048), write split-bf16 P.
__global__ void __launch_bounds__(256)
softmax_split_kernel(const float* __restrict__ S, __nv_bfloat16* __restrict__ Ph,
                     __nv_bfloat16* __restrict__ Pl)
{
    const long row = blockIdx.x;
    const float* p = S + row * (long)N_;
    const int tid = threadIdx.x;

    float v[8];
    float mx = -1e30f;
    #pragma unroll
    for (int i = 0; i < 8; i++) { v[i] = p[tid + i * 256]; mx = fmaxf(mx, v[i]); }

    __shared__ float redm[8], reds[8];
    #pragma unroll
    for (int o = 16; o; o >>= 1) mx = fmaxf(mx, __shfl_xor_sync(0xffffffffu, mx, o));
    if ((tid & 31) == 0) redm[tid >> 5] = mx;
    __syncthreads();
    if (tid == 0) {
        float m = redm[0];
        #pragma unroll
        for (int i = 1; i < 8; i++) m = fmaxf(m, redm[i]);
        redm[0] = m;
    }
    __syncthreads();
    mx = redm[0];

    float s = 0.0f;
    #pragma unroll
    for (int i = 0; i < 8; i++) { v[i] = __expf(v[i] - mx); s += v[i]; }
    #pragma unroll
    for (int o = 16; o; o >>= 1) s += __shfl_xor_sync(0xffffffffu, s, o);
    if ((tid & 31) == 0) reds[tid >> 5] = s;
    __syncthreads();
    if (tid == 0) {
        float m = 0.0f;
        #pragma unroll
        for (int i = 0; i < 8; i++) m += reds[i];
        reds[0] = m;
    }
    __syncthreads();
    const float inv = 1.0f / reds[0];

    #pragma unroll
    for (int i = 0; i < 8; i++) {
        float w = v[i] * inv;
        __nv_bfloat16 h = __float2bfloat16(w);
        __nv_bfloat16 l = __float2bfloat16(w - __bfloat162float(h));
        Ph[row * (long)N_ + tid + i * 256] = h;
        Pl[row * (long)N_ + tid + i * 256] = l;
    }
}

// ================= host glue =================
extern "C" void kernel_launch(void* const* d_in, const int* in_sizes, int n_in,
                              void* d_out, int out_size)
{
    const float* X  = (const float*)d_in[0];
    const float* Wq = (const float*)d_in[1];
    const float* bq = (const float*)d_in[2];
    const float* Wk = (const float*)d_in[3];
    const float* bk = (const float*)d_in[4];
    const float* Wv = (const float*)d_in[5];
    const float* bv = (const float*)d_in[6];
    float* out = (float*)d_out;

    __nv_bfloat16 *Xh, *Xl, *Qh, *Ql, *Kh, *Kl, *Vh, *Vl, *Vth, *Vtl;
    __nv_bfloat16 *Wqth, *Wqtl, *Wkth, *Wktl, *Wvth, *Wvtl, *Ph, *Pl;
    float* S;
    cudaGetSymbolAddress((void**)&Xh, g_Xh);   cudaGetSymbolAddress((void**)&Xl, g_Xl);
    cudaGetSymbolAddress((void**)&Qh, g_Qh);   cudaGetSymbolAddress((void**)&Ql, g_Ql);
    cudaGetSymbolAddress((void**)&Kh, g_Kh);   cudaGetSymbolAddress((void**)&Kl, g_Kl);
    cudaGetSymbolAddress((void**)&Vh, g_Vh);   cudaGetSymbolAddress((void**)&Vl, g_Vl);
    cudaGetSymbolAddress((void**)&Vth, g_Vth); cudaGetSymbolAddress((void**)&Vtl, g_Vtl);
    cudaGetSymbolAddress((void**)&Wqth, g_Wqth); cudaGetSymbolAddress((void**)&Wqtl, g_Wqtl);
    cudaGetSymbolAddress((void**)&Wkth, g_Wkth); cudaGetSymbolAddress((void**)&Wktl, g_Wktl);
    cudaGetSymbolAddress((void**)&Wvth, g_Wvth); cudaGetSymbolAddress((void**)&Wvtl, g_Wvtl);
    cudaGetSymbolAddress((void**)&Ph, g_Ph);   cudaGetSymbolAddress((void**)&Pl, g_Pl);
    cudaGetSymbolAddress((void**)&S, g_S);

    cudaFuncSetAttribute((const void*)qkv_gemm,      cudaFuncAttributeMaxDynamicSharedMemorySize, (int)SMEM_BYTES);
    cudaFuncSetAttribute((const void*)tc_gemm<0, 0>, cudaFuncAttributeMaxDynamicSharedMemorySize, (int)SMEM_BYTES);

    dim3 blk(256);

    // 0) split X, transpose+split weights
    split_x_kernel<<<(MTOT * D_) / 1024, 256>>>(X, Xh, Xl);
    transpose_split_kernel<<<dim3(32, 32, 3), dim3(32, 8)>>>(
        Wq, Wk, Wv, Wqth, Wqtl, Wkth, Wktl, Wvth, Wvtl);

    // 1) fused QKV projection: one launch, 1536 CTAs (z = q/k/v)
    qkv_gemm<<<dim3(8, 64, 3), blk, SMEM_BYTES>>>(
        Xh, Xl, Wqth, Wqtl, Wkth, Wktl, Wvth, Wvtl,
        bq, bk, bv, Qh, Ql, Kh, Kl, Vh, Vl);

    // 1b) transpose V planes for the NT PV GEMM
    transpose_v_kernel<<<dim3(32, 256, 2), dim3(32, 8)>>>(Vh, Vl, Vth, Vtl);

    // 2) S = Q K^T per batch (fp32)
    tc_gemm<0, 0><<<dim3(16, 16, B_), blk, SMEM_BYTES>>>(
        Qh, Ql, D_, (long)N_ * D_, Kh, Kl, D_, (long)N_ * D_,
        S, nullptr, nullptr, N_, (long)N_ * N_, nullptr, D_);

    // 3) softmax + split P
    softmax_split_kernel<<<B_ * N_, 256>>>(S, Ph, Pl);

    // 4) out = P V per batch (NT against V^T, fp32 out)
    tc_gemm<0, 0><<<dim3(8, 16, B_), blk, SMEM_BYTES>>>(
        Ph, Pl, N_, (long)N_ * N_, Vth, Vtl, MTOT, (long)N_,
        out, nullptr, nullptr, D_, (long)N_ * D_, nullptr, N_);
}